// round 7
// baseline (speedup 1.0000x reference)
#include <cuda_runtime.h>

typedef unsigned long long u64;

static __device__ __forceinline__ u64 pk2(float lo, float hi) {
    u64 r; asm("mov.b64 %0,{%1,%2};" : "=l"(r) : "f"(lo), "f"(hi)); return r;
}
static __device__ __forceinline__ void unpk(u64 v, float &lo, float &hi) {
    asm("mov.b64 {%0,%1}, %2;" : "=f"(lo), "=f"(hi) : "l"(v));
}
static __device__ __forceinline__ void ffma2(u64 &d, u64 a, u64 b) {
    asm("fma.rn.f32x2 %0, %1, %2, %0;" : "+l"(d) : "l"(a), "l"(b));
}

// ------------------------------ scratch ------------------------------------
// A2[b][p][q][384]: blocks (s1,s2,s3,d12,d13,d23), each 64 channels.
__device__ float g_A2[8 * 32 * 32 * 384];      // 12.6 MB
__device__ float g_A1[8 * 32 * 640];           // a1 [B,n,10C]
__device__ float g_A0[8 * 320];                // a0 [B,5C]
__device__ float g_R12 [3 * 8 * 32 * 64];      // a1@W12[i]+b12[i]   (indexed by t)
__device__ float g_R12t[3 * 8 * 32 * 64];      // a1@W12t[i]+b12t[i] (indexed by d)
__device__ float g_R02b[3 * 8 * 64];           // a0@W02[i]+b02[i]+b22[i]
__device__ float g_Rmd [8 * 32 * 64];          // a1@W11+b11 + a0@W01+b01
__device__ float g_S[3 * 8 * 32 * 32 * 64];    // slices [i][b][t][d][64]

// ----------------- K1: second-order contractions into A2 --------------------
// grid (256, 6): x = b*32+P, y = kind. 256 threads, 8 elems each.
__global__ void k_contract(const float* __restrict__ x) {
    const int kind = blockIdx.y;
    const int b = blockIdx.x >> 5, P = blockIdx.x & 31;
    const int tid = threadIdx.x;
    const float* xb = x + b * 2097152;
#pragma unroll
    for (int r = 0; r < 8; r++) {
        const int idx = r * 256 + tid;
        const int e = idx >> 6, c = idx & 63;
        float v;
        if (kind == 0) {            // s1[b,P=j,Q=k] = mean_i x[b,i,P,e]
            const float* p = xb + P * 2048 + e * 64 + c;
            float s = 0.f;
#pragma unroll
            for (int i = 0; i < 32; i++) s += p[i * 65536];
            v = s * 0.03125f;
        } else if (kind == 1) {     // s2[b,P=i,Q=k] = mean_j x[b,P,j,e]
            const float* p = xb + P * 65536 + e * 64 + c;
            float s = 0.f;
#pragma unroll
            for (int j = 0; j < 32; j++) s += p[j * 2048];
            v = s * 0.03125f;
        } else if (kind == 2) {     // s3[b,P=i,Q=j] = mean_k x[b,P,e,k]
            const float* p = xb + P * 65536 + e * 2048 + c;
            float s = 0.f;
#pragma unroll
            for (int k = 0; k < 32; k++) s += p[k * 64];
            v = s * 0.03125f;
        } else if (kind == 3) {     // d12[b,P=t,Q=d] = x[b,d,d,t]
            v = xb[e * 65536 + e * 2048 + P * 64 + c];
        } else if (kind == 4) {     // d13[b,P=t,Q=d] = x[b,d,t,d]
            v = xb[e * 65536 + P * 2048 + e * 64 + c];
        } else {                    // d23[b,P=t,Q=d] = x[b,t,d,d]
            v = xb[P * 65536 + e * 2048 + e * 64 + c];
        }
        g_A2[((b * 32 + P) * 32 + e) * 384 + kind * 64 + c] = v;
    }
}

// ----------------- K2: a1 from A2. grid (8, 10), 256 threads ----------------
__global__ void k_a1() {
    const int b = blockIdx.x, blk = blockIdx.y;
    const int tid = threadIdx.x;
    const int t = tid >> 3, c0 = (tid & 7) * 8;
    int off, axis;  // axis 0: mean over p of A2[b,p,t]; 1: mean over q of A2[b,t,q]; 2: diag
    switch (blk) {
        case 0: off = 0;   axis = 0; break;  // x.mean((1,2))
        case 1: off = 0;   axis = 1; break;  // x.mean((1,3))
        case 2: off = 64;  axis = 1; break;  // x.mean((2,3))
        case 3: off = 192; axis = 0; break;  // d12.mean(1)
        case 4: off = 192; axis = 1; break;  // d12.mean(2)
        case 5: off = 256; axis = 0; break;  // d13.mean(1)
        case 6: off = 256; axis = 1; break;  // d13.mean(2)
        case 7: off = 320; axis = 0; break;  // d23.mean(1)
        case 8: off = 320; axis = 1; break;  // d23.mean(2)
        default: off = 320; axis = 2; break; // tdiag
    }
#pragma unroll
    for (int e = 0; e < 8; e++) {
        const int c = c0 + e;
        float s = 0.f;
        if (axis == 2) {
            s = g_A2[((b * 32 + t) * 32 + t) * 384 + off + c];
        } else if (axis == 0) {
            for (int p = 0; p < 32; p++) s += g_A2[((b * 32 + p) * 32 + t) * 384 + off + c];
            s *= 0.03125f;
        } else {
            for (int q = 0; q < 32; q++) s += g_A2[((b * 32 + t) * 32 + q) * 384 + off + c];
            s *= 0.03125f;
        }
        g_A1[(b * 32 + t) * 640 + blk * 64 + c] = s;
    }
}

// ----------------- K2b: a0 from a1. grid 8, 256 threads ---------------------
__global__ void k_a0() {
    const int b = blockIdx.x;
    const int srcmap[5] = {2, 4, 6, 8, 9};
    for (int idx = threadIdx.x; idx < 320; idx += 256) {
        const int blk = idx >> 6, c = idx & 63;
        const int so = srcmap[blk] * 64 + c;
        float s = 0.f;
        for (int t = 0; t < 32; t++) s += g_A1[(b * 32 + t) * 640 + so];
        g_A0[b * 320 + idx] = s * 0.03125f;
    }
}

// ----------------- K4: vector mixes. grid (32, 8), 64 threads ---------------
__global__ void k_vec(const float* __restrict__ W12, const float* __restrict__ b12,
                      const float* __restrict__ W12t, const float* __restrict__ b12t,
                      const float* __restrict__ W02, const float* __restrict__ b02,
                      const float* __restrict__ W11, const float* __restrict__ b11,
                      const float* __restrict__ W01, const float* __restrict__ b01,
                      const float* __restrict__ b22) {
    const int y = blockIdx.y;
    const int o = threadIdx.x;
    const int bt0 = blockIdx.x * 8;
    const float* A1 = (const float*)g_A1;
    const float* A0 = (const float*)g_A0;
    if (y < 6) {
        const int i = (y < 3) ? y : (y - 3);
        const float* W = ((y < 3) ? W12 : W12t) + i * 40960;
        const float bias = (y < 3) ? b12[i * 64 + o] : b12t[i * 64 + o];
        float acc[8];
#pragma unroll
        for (int r = 0; r < 8; r++) acc[r] = bias;
        for (int k = 0; k < 640; k++) {
            const float w = __ldg(W + k * 64 + o);
#pragma unroll
            for (int r = 0; r < 8; r++) acc[r] += __ldg(A1 + (bt0 + r) * 640 + k) * w;
        }
        float* dst = (y < 3) ? g_R12 : g_R12t;
#pragma unroll
        for (int r = 0; r < 8; r++) dst[(i * 256 + bt0 + r) * 64 + o] = acc[r];
    } else if (y == 6) {
        float acc[8];
#pragma unroll
        for (int r = 0; r < 8; r++) acc[r] = b11[o] + b01[o];
        for (int k = 0; k < 640; k++) {
            const float w = __ldg(W11 + k * 64 + o);
#pragma unroll
            for (int r = 0; r < 8; r++) acc[r] += __ldg(A1 + (bt0 + r) * 640 + k) * w;
        }
        for (int k = 0; k < 320; k++) {
            const float w = __ldg(W01 + k * 64 + o);
#pragma unroll
            for (int r = 0; r < 8; r++) acc[r] += __ldg(A0 + ((bt0 + r) >> 5) * 320 + k) * w;
        }
#pragma unroll
        for (int r = 0; r < 8; r++) g_Rmd[(bt0 + r) * 64 + o] = acc[r];
    } else {
        for (int r = 0; r < 8; r++) {
            const int bt = bt0 + r, t = bt & 31, b = bt >> 5;
            if (t < 3) {
                const int i = t;
                float s = b22[i * 64 + o] + b02[i * 64 + o];
                const float* W = W02 + i * 20480;
                for (int k = 0; k < 320; k++)
                    s += __ldg(A0 + b * 320 + k) * __ldg(W + k * 64 + o);
                g_R02b[(i * 8 + b) * 64 + o] = s;
            }
        }
    }
}

// ----------------- K3: main GEMM  T = allp @ W33 + b33 ----------------------
// grid 148 (one persistent block per SM), 256 threads,
// 149KB dyn smem: wsh[384*64] + xsh[384*33].
__global__ void k_main(const float* __restrict__ x, const float* __restrict__ W33,
                       const float* __restrict__ b33, float* __restrict__ out) {
    extern __shared__ float sm[];
    float* wsh = sm;            // 24576 floats
    float* xsh = sm + 24576;    // 12672 floats
    const int tid = threadIdx.x;
    const int warp = tid >> 5, lane = tid & 31;
    const int o0 = warp * 8;

    const float4* W4 = (const float4*)W33;
    float4* wsh4 = (float4*)wsh;
    for (int idx = tid; idx < 6144; idx += 256) wsh4[idx] = W4[idx];

    const float4* x4 = (const float4*)x;
    float4* out4 = (float4*)out;

    const float bb0 = __ldg(b33 + o0 + 0), bb1 = __ldg(b33 + o0 + 1);
    const float bb2 = __ldg(b33 + o0 + 2), bb3 = __ldg(b33 + o0 + 3);
    const float bb4 = __ldg(b33 + o0 + 4), bb5 = __ldg(b33 + o0 + 5);
    const float bb6 = __ldg(b33 + o0 + 6), bb7 = __ldg(b33 + o0 + 7);

    __syncthreads();

    for (int pen = blockIdx.x; pen < 8192; pen += gridDim.x) {
        const int b = pen >> 10, i = (pen >> 5) & 31, j = pen & 31;
        // stage the 6 permutation pencils: xsh[cc][k], cc = p*64+c
        for (int idx = tid; idx < 3072; idx += 256) {
            const int p = idx >> 9, rem = idx & 511, k = rem >> 4, c4 = rem & 15;
            int A, B, C;
            switch (p) {
                case 0: A = i; B = j; C = k; break;   // x[b,i,j,k]
                case 1: A = i; B = k; C = j; break;   // x[b,i,k,j]
                case 2: A = j; B = i; C = k; break;   // x[b,j,i,k]
                case 3: A = k; B = i; C = j; break;   // x[b,k,i,j]
                case 4: A = j; B = k; C = i; break;   // x[b,j,k,i]
                default: A = k; B = j; C = i; break;  // x[b,k,j,i]
            }
            const float4 v = x4[b * 524288 + A * 16384 + B * 512 + C * 16 + c4];
            const int cc = p * 64 + c4 * 4;
            xsh[(cc + 0) * 33 + k] = v.x;
            xsh[(cc + 1) * 33 + k] = v.y;
            xsh[(cc + 2) * 33 + k] = v.z;
            xsh[(cc + 3) * 33 + k] = v.w;
        }
        __syncthreads();

        u64 acc0 = pk2(bb0, bb1), acc1 = pk2(bb2, bb3);
        u64 acc2 = pk2(bb4, bb5), acc3 = pk2(bb6, bb7);
#pragma unroll 8
        for (int cc = 0; cc < 384; cc++) {
            const float* wr = wsh + cc * 64 + o0;
            const u64 w0 = *(const u64*)(wr + 0);
            const u64 w1 = *(const u64*)(wr + 2);
            const u64 w2 = *(const u64*)(wr + 4);
            const u64 w3 = *(const u64*)(wr + 6);
            const float xv = xsh[cc * 33 + lane];
            const u64 xx = pk2(xv, xv);
            ffma2(acc0, xx, w0); ffma2(acc1, xx, w1);
            ffma2(acc2, xx, w2); ffma2(acc3, xx, w3);
        }
        float4 r0, r1;
        unpk(acc0, r0.x, r0.y); unpk(acc1, r0.z, r0.w);
        unpk(acc2, r1.x, r1.y); unpk(acc3, r1.z, r1.w);
        const int ob = pen * 512 + lane * 16 + (o0 >> 2);
        out4[ob] = r0; out4[ob + 1] = r1;
        __syncthreads();
    }
}

// ----------------- K5: slice GEMM  slices[i] = a2wt @ W22[i] + terms --------
// grid 768 (i*256 + b*32 + t), 256 threads, 149KB dyn smem.
__global__ void k_slice(const float* __restrict__ W22) {
    extern __shared__ float sm[];
    float* wsh = sm;
    float* ash = sm + 24576;
    const int bid = blockIdx.x;
    const int i = bid >> 8, b = (bid >> 5) & 7, t = bid & 31;
    const int tid = threadIdx.x;
    const int warp = tid >> 5, lane = tid & 31;
    const int o0 = warp * 8;

    float bo[8];
#pragma unroll
    for (int e = 0; e < 8; e++) {
        const int o = o0 + e;
        bo[e] = g_R12[((i * 8 + b) * 32 + t) * 64 + o]
              + g_R12t[((i * 8 + b) * 32 + lane) * 64 + o]
              + g_R02b[(i * 8 + b) * 64 + o];
    }
    u64 acc0 = pk2(bo[0], bo[1]), acc1 = pk2(bo[2], bo[3]);
    u64 acc2 = pk2(bo[4], bo[5]), acc3 = pk2(bo[6], bo[7]);

    const float4* W4 = (const float4*)(W22 + i * 49152);
    const float4* A24 = (const float4*)g_A2;

    for (int tile = 0; tile < 2; tile++) {
        for (int idx = tid; idx < 6144; idx += 256)
            ((float4*)wsh)[idx] = W4[tile * 6144 + idx];
        for (int idx = tid; idx < 3072; idx += 256) {
            const int d = idx / 96, c4 = idx % 96;
            const int P = tile ? d : t, Q = tile ? t : d;
            const float4 v = A24[((b * 32 + P) * 32 + Q) * 96 + c4];
            const int cc = c4 * 4;
            ash[(cc + 0) * 33 + d] = v.x;
            ash[(cc + 1) * 33 + d] = v.y;
            ash[(cc + 2) * 33 + d] = v.z;
            ash[(cc + 3) * 33 + d] = v.w;
        }
        __syncthreads();
#pragma unroll 8
        for (int cc = 0; cc < 384; cc++) {
            const float* wr = wsh + cc * 64 + o0;
            const u64 w0 = *(const u64*)(wr + 0);
            const u64 w1 = *(const u64*)(wr + 2);
            const u64 w2 = *(const u64*)(wr + 4);
            const u64 w3 = *(const u64*)(wr + 6);
            const float xv = ash[cc * 33 + lane];
            const u64 xx = pk2(xv, xv);
            ffma2(acc0, xx, w0); ffma2(acc1, xx, w1);
            ffma2(acc2, xx, w2); ffma2(acc3, xx, w3);
        }
        __syncthreads();
    }
    float4 r0, r1;
    unpk(acc0, r0.x, r0.y); unpk(acc1, r0.z, r0.w);
    unpk(acc2, r1.x, r1.y); unpk(acc3, r1.z, r1.w);
    float4* S4 = (float4*)g_S;
    const int ob = (((i * 8 + b) * 32 + t) * 32 + lane) * 16 + (o0 >> 2);
    S4[ob] = r0; S4[ob + 1] = r1;
}

// ----------------- K6: diagonal scatter-add. grid 256, 256 threads ----------
__global__ void k_scatter(float* __restrict__ out) {
    const int bt = blockIdx.x;
    const int b = bt >> 5, t = bt & 31;
    const int tid = threadIdx.x;
    const int dg = tid >> 6, c = tid & 63;
    const float* S0 = g_S + ((0 * 8 + b) * 32 + t) * 2048;
    const float* S1 = g_S + ((1 * 8 + b) * 32 + t) * 2048;
    const float* S2 = g_S + ((2 * 8 + b) * 32 + t) * 2048;
    float* ob = out + b * 2097152;
    for (int d = dg; d < 32; d += 4) {
        const float s0 = S0[d * 64 + c], s1 = S1[d * 64 + c], s2 = S2[d * 64 + c];
        if (d != t) {
            ob[d * 65536 + d * 2048 + t * 64 + c] += s0;   // T[b,d,d,t]
            ob[d * 65536 + t * 2048 + d * 64 + c] += s1;   // T[b,d,t,d]
            ob[t * 65536 + d * 2048 + d * 64 + c] += s2;   // T[b,t,d,d]
        } else {
            ob[d * 65536 + d * 2048 + d * 64 + c] += s0 + s1 + s2 + g_Rmd[(b * 32 + d) * 64 + c];
        }
    }
}

// ---------------------------------------------------------------------------
extern "C" void kernel_launch(void* const* d_in, const int* in_sizes, int n_in,
                              void* d_out, int out_size) {
    const float* x    = (const float*)d_in[0];
    const float* W33  = (const float*)d_in[1];
    const float* b33  = (const float*)d_in[2];
    const float* W22  = (const float*)d_in[3];
    const float* b22  = (const float*)d_in[4];
    const float* W12  = (const float*)d_in[5];
    const float* b12  = (const float*)d_in[6];
    const float* W12t = (const float*)d_in[7];
    const float* b12t = (const float*)d_in[8];
    const float* W02  = (const float*)d_in[9];
    const float* b02  = (const float*)d_in[10];
    const float* W11  = (const float*)d_in[11];
    const float* b11  = (const float*)d_in[12];
    const float* W01  = (const float*)d_in[13];
    const float* b01  = (const float*)d_in[14];
    float* out = (float*)d_out;

    const size_t smbytes = (24576 + 384 * 33) * sizeof(float);  // 148992
    cudaFuncSetAttribute(k_main,  cudaFuncAttributeMaxDynamicSharedMemorySize, (int)smbytes);
    cudaFuncSetAttribute(k_slice, cudaFuncAttributeMaxDynamicSharedMemorySize, (int)smbytes);

    k_contract<<<dim3(256, 6), 256>>>(x);
    k_a1<<<dim3(8, 10), 256>>>();
    k_a0<<<8, 256>>>();
    k_vec<<<dim3(32, 8), 64>>>(W12, b12, W12t, b12t, W02, b02, W11, b11, W01, b01, b22);
    k_main<<<148, 256, smbytes>>>(x, W33, b33, out);
    k_slice<<<768, 256, smbytes>>>(W22);
    k_scatter<<<256, 256>>>(out);
}

// round 9
// speedup vs baseline: 1.5957x; 1.5957x over previous
#include <cuda_runtime.h>

typedef unsigned long long u64;

static __device__ __forceinline__ u64 pk2(float lo, float hi) {
    u64 r; asm("mov.b64 %0,{%1,%2};" : "=l"(r) : "f"(lo), "f"(hi)); return r;
}
static __device__ __forceinline__ void unpk(u64 v, float &lo, float &hi) {
    asm("mov.b64 {%0,%1}, %2;" : "=f"(lo), "=f"(hi) : "l"(v));
}
static __device__ __forceinline__ void ffma2(u64 &d, u64 a, u64 b) {
    asm("fma.rn.f32x2 %0, %1, %2, %0;" : "+l"(d) : "l"(a), "l"(b));
}

// ------------------------------ scratch ------------------------------------
__device__ float g_A2[8 * 32 * 32 * 384];      // blocks (s1,s2,s3,d12,d13,d23)
__device__ float g_A1[8 * 32 * 640];           // a1 [B,n,10C]
__device__ float g_A0[8 * 320];                // a0 [B,5C]
__device__ float g_R12 [3 * 8 * 32 * 64];      // a1@W12[i]+b12[i]   (by t)
__device__ float g_R12t[3 * 8 * 32 * 64];      // a1@W12t[i]+b12t[i] (by d)
__device__ float g_R02b[3 * 8 * 64];           // a0@W02[i]+b02[i]+b22[i]
__device__ float g_Rmd [8 * 32 * 64];          // a1@W11+b11 + a0@W01+b01
__device__ float g_S[3 * 8 * 32 * 32 * 64];    // slices [i][b][t][d][64]

// ----------------- K1: second-order contractions into A2 --------------------
// grid (256, 3): x = b*32+P.  y=0: s1; y=1: s2+s3 fused single pass; y=2: diags.
__global__ void k_contract(const float* __restrict__ x) {
    const int y = blockIdx.y;
    const int b = blockIdx.x >> 5, P = blockIdx.x & 31;
    const int tid = threadIdx.x;
    const float* xb = x + b * 2097152;
    if (y == 0) {
        // s1[b,P=j,Q=k,c] = mean_i x[b,i,P,k,c]
#pragma unroll
        for (int r = 0; r < 8; r++) {
            const int idx = r * 256 + tid;
            const int e = idx >> 6, c = idx & 63;
            const float* p = xb + P * 2048 + e * 64 + c;
            float s = 0.f;
#pragma unroll
            for (int i = 0; i < 32; i++) s += p[i * 65536];
            g_A2[((b * 32 + P) * 32 + e) * 384 + 0 + c] = s * 0.03125f;
        }
    } else if (y == 1) {
        // one pass over plane x[b,P,:,:,:]: s2 (sum over j) + s3 (sum over k)
        __shared__ float ps3[4 * 32 * 64];   // partial s3 per qs group (32KB)
        const int c = tid & 63, qs = tid >> 6;
        float s2acc[8] = {0, 0, 0, 0, 0, 0, 0, 0};
        const float* base = xb + P * 65536;
        for (int j = 0; j < 32; j++) {
            float t = 0.f;
#pragma unroll
            for (int kk = 0; kk < 8; kk++) {
                const int k = qs + kk * 4;
                const float v = base[j * 2048 + k * 64 + c];
                s2acc[kk] += v; t += v;
            }
            ps3[(qs * 32 + j) * 64 + c] = t;
        }
        __syncthreads();
#pragma unroll
        for (int kk = 0; kk < 8; kk++) {
            const int k = qs + kk * 4;
            g_A2[((b * 32 + P) * 32 + k) * 384 + 64 + c] = s2acc[kk] * 0.03125f;
        }
        for (int idx = tid; idx < 2048; idx += 256) {
            const int j = idx >> 6, cc = idx & 63;
            const float s = ps3[j * 64 + cc] + ps3[2048 + j * 64 + cc]
                          + ps3[4096 + j * 64 + cc] + ps3[6144 + j * 64 + cc];
            g_A2[((b * 32 + P) * 32 + j) * 384 + 128 + cc] = s * 0.03125f;
        }
    } else {
        // diagonals d12,d13,d23
        for (int idx = tid; idx < 6144; idx += 256) {
            const int kind = idx >> 11;            // 0,1,2
            const int e = (idx >> 6) & 31, c = idx & 63;
            float v;
            if (kind == 0)      v = xb[e * 65536 + e * 2048 + P * 64 + c];  // d12: x[b,d,d,t]
            else if (kind == 1) v = xb[e * 65536 + P * 2048 + e * 64 + c];  // d13: x[b,d,t,d]
            else                v = xb[P * 65536 + e * 2048 + e * 64 + c];  // d23: x[b,t,d,d]
            g_A2[((b * 32 + P) * 32 + e) * 384 + (3 + kind) * 64 + c] = v;
        }
    }
}

// ----------------- K2: a1 from A2. grid (8, 10), 256 threads ----------------
__global__ void k_a1() {
    const int b = blockIdx.x, blk = blockIdx.y;
    const int tid = threadIdx.x;
    const int t = tid >> 3, c0 = (tid & 7) * 8;
    int off, axis;
    switch (blk) {
        case 0: off = 0;   axis = 0; break;
        case 1: off = 0;   axis = 1; break;
        case 2: off = 64;  axis = 1; break;
        case 3: off = 192; axis = 0; break;
        case 4: off = 192; axis = 1; break;
        case 5: off = 256; axis = 0; break;
        case 6: off = 256; axis = 1; break;
        case 7: off = 320; axis = 0; break;
        case 8: off = 320; axis = 1; break;
        default: off = 320; axis = 2; break;
    }
#pragma unroll
    for (int e = 0; e < 8; e++) {
        const int c = c0 + e;
        float s = 0.f;
        if (axis == 2) {
            s = g_A2[((b * 32 + t) * 32 + t) * 384 + off + c];
        } else if (axis == 0) {
            for (int p = 0; p < 32; p++) s += g_A2[((b * 32 + p) * 32 + t) * 384 + off + c];
            s *= 0.03125f;
        } else {
            for (int q = 0; q < 32; q++) s += g_A2[((b * 32 + t) * 32 + q) * 384 + off + c];
            s *= 0.03125f;
        }
        g_A1[(b * 32 + t) * 640 + blk * 64 + c] = s;
    }
}

// ----------------- K2b: a0 from a1. grid 8, 256 threads ---------------------
__global__ void k_a0() {
    const int b = blockIdx.x;
    const int srcmap[5] = {2, 4, 6, 8, 9};
    for (int idx = threadIdx.x; idx < 320; idx += 256) {
        const int blk = idx >> 6, c = idx & 63;
        const int so = srcmap[blk] * 64 + c;
        float s = 0.f;
        for (int t = 0; t < 32; t++) s += g_A1[(b * 32 + t) * 640 + so];
        g_A0[b * 320 + idx] = s * 0.03125f;
    }
}

// ----------------- K4: vector mixes. grid (256, 7), 256 threads -------------
// y<3: R12[i=y]; y<6: R12t[i=y-3]; y==6: Rmd (+R02b when t<3).
__global__ void k_vec(const float* __restrict__ W12, const float* __restrict__ b12,
                      const float* __restrict__ W12t, const float* __restrict__ b12t,
                      const float* __restrict__ W02, const float* __restrict__ b02,
                      const float* __restrict__ W11, const float* __restrict__ b11,
                      const float* __restrict__ W01, const float* __restrict__ b01,
                      const float* __restrict__ b22) {
    __shared__ float a1sh[640];
    __shared__ float a0sh[320];
    __shared__ float psum[4][64];
    __shared__ float psum2[4][64];
    const int row = blockIdx.x;            // b*32 + t
    const int y = blockIdx.y;
    const int tid = threadIdx.x;
    const int o = tid & 63, chunk = tid >> 6;
    const int b = row >> 5, t = row & 31;

    for (int idx = tid; idx < 640; idx += 256) a1sh[idx] = g_A1[row * 640 + idx];
    if (y == 6) for (int idx = tid; idx < 320; idx += 256) a0sh[idx] = g_A0[b * 320 + idx];
    __syncthreads();

    const float* W; float* dst;
    if (y < 3)      { W = W12  + y * 40960;        dst = g_R12  + (y * 256 + row) * 64; }
    else if (y < 6) { W = W12t + (y - 3) * 40960;  dst = g_R12t + ((y - 3) * 256 + row) * 64; }
    else            { W = W11;                     dst = g_Rmd + row * 64; }

    float acc = 0.f;
    const int k0 = chunk * 160;
#pragma unroll 8
    for (int k = k0; k < k0 + 160; k++)
        acc += a1sh[k] * __ldg(W + k * 64 + o);
    if (y == 6) {
#pragma unroll 8
        for (int k = chunk * 80; k < chunk * 80 + 80; k++)
            acc += a0sh[k] * __ldg(W01 + k * 64 + o);
    }
    psum[chunk][o] = acc;

    if (y == 6 && t < 3) {
        float acc2 = 0.f;
#pragma unroll 8
        for (int k = chunk * 80; k < chunk * 80 + 80; k++)
            acc2 += a0sh[k] * __ldg(W02 + t * 20480 + k * 64 + o);
        psum2[chunk][o] = acc2;
    }
    __syncthreads();
    if (chunk == 0) {
        float s = psum[0][o] + psum[1][o] + psum[2][o] + psum[3][o];
        if (y < 3)      s += __ldg(b12  + y * 64 + o);
        else if (y < 6) s += __ldg(b12t + (y - 3) * 64 + o);
        else            s += __ldg(b11 + o) + __ldg(b01 + o);
        dst[o] = s;
        if (y == 6 && t < 3) {
            float s2 = psum2[0][o] + psum2[1][o] + psum2[2][o] + psum2[3][o]
                     + __ldg(b02 + t * 64 + o) + __ldg(b22 + t * 64 + o);
            g_R02b[(t * 8 + b) * 64 + o] = s2;
        }
    }
}

// ----------------- K3: main GEMM  T = allp @ W33 + b33 ----------------------
// grid 148 persistent, 256 threads. smem: wsh[384*64] + 2 x xsh[384*33] = 199.7KB.
// Two pencils per iteration: W smem-loads amortized across both.
__global__ void k_main(const float* __restrict__ x, const float* __restrict__ W33,
                       const float* __restrict__ b33, float* __restrict__ out) {
    extern __shared__ float sm[];
    float* wsh  = sm;                   // 24576
    float* xshA = sm + 24576;           // 12672
    float* xshB = sm + 24576 + 12672;   // 12672
    const int tid = threadIdx.x;
    const int warp = tid >> 5, lane = tid & 31;
    const int o0 = warp * 8;

    const float4* W4 = (const float4*)W33;
    float4* wsh4 = (float4*)wsh;
    for (int idx = tid; idx < 6144; idx += 256) wsh4[idx] = W4[idx];

    const float4* x4 = (const float4*)x;
    float4* out4 = (float4*)out;

    const float bb0 = __ldg(b33 + o0 + 0), bb1 = __ldg(b33 + o0 + 1);
    const float bb2 = __ldg(b33 + o0 + 2), bb3 = __ldg(b33 + o0 + 3);
    const float bb4 = __ldg(b33 + o0 + 4), bb5 = __ldg(b33 + o0 + 5);
    const float bb6 = __ldg(b33 + o0 + 6), bb7 = __ldg(b33 + o0 + 7);

    __syncthreads();

    for (int pair = blockIdx.x; pair < 4096; pair += gridDim.x) {
        const int pen0 = pair * 2;
        const int b = pen0 >> 10, i = (pen0 >> 5) & 31, j0 = pen0 & 31;
        // stage 6 permutation pencils for both pencils (j0, j0+1)
        for (int idx = tid; idx < 6144; idx += 256) {
            const int half = idx / 3072;
            const int id2 = idx - half * 3072;
            const int p = id2 >> 9, rem = id2 & 511, k = rem >> 4, c4 = rem & 15;
            const int j = j0 + half;
            int A, B, C;
            switch (p) {
                case 0: A = i; B = j; C = k; break;
                case 1: A = i; B = k; C = j; break;
                case 2: A = j; B = i; C = k; break;
                case 3: A = k; B = i; C = j; break;
                case 4: A = j; B = k; C = i; break;
                default: A = k; B = j; C = i; break;
            }
            const float4 v = x4[b * 524288 + A * 16384 + B * 512 + C * 16 + c4];
            float* xs = half ? xshB : xshA;
            const int cc = p * 64 + c4 * 4;
            xs[(cc + 0) * 33 + k] = v.x;
            xs[(cc + 1) * 33 + k] = v.y;
            xs[(cc + 2) * 33 + k] = v.z;
            xs[(cc + 3) * 33 + k] = v.w;
        }
        __syncthreads();

        u64 aA0 = pk2(bb0, bb1), aA1 = pk2(bb2, bb3);
        u64 aA2 = pk2(bb4, bb5), aA3 = pk2(bb6, bb7);
        u64 aB0 = aA0, aB1 = aA1, aB2 = aA2, aB3 = aA3;
#pragma unroll 4
        for (int cc = 0; cc < 384; cc++) {
            const float* wr = wsh + cc * 64 + o0;
            const u64 w0 = *(const u64*)(wr + 0);
            const u64 w1 = *(const u64*)(wr + 2);
            const u64 w2 = *(const u64*)(wr + 4);
            const u64 w3 = *(const u64*)(wr + 6);
            const float xa = xshA[cc * 33 + lane];
            const float xb_ = xshB[cc * 33 + lane];
            const u64 xa2 = pk2(xa, xa);
            const u64 xb2 = pk2(xb_, xb_);
            ffma2(aA0, xa2, w0); ffma2(aA1, xa2, w1);
            ffma2(aA2, xa2, w2); ffma2(aA3, xa2, w3);
            ffma2(aB0, xb2, w0); ffma2(aB1, xb2, w1);
            ffma2(aB2, xb2, w2); ffma2(aB3, xb2, w3);
        }
        float4 r0, r1;
        unpk(aA0, r0.x, r0.y); unpk(aA1, r0.z, r0.w);
        unpk(aA2, r1.x, r1.y); unpk(aA3, r1.z, r1.w);
        int ob = pen0 * 512 + lane * 16 + (o0 >> 2);
        out4[ob] = r0; out4[ob + 1] = r1;
        unpk(aB0, r0.x, r0.y); unpk(aB1, r0.z, r0.w);
        unpk(aB2, r1.x, r1.y); unpk(aB3, r1.z, r1.w);
        ob += 512;
        out4[ob] = r0; out4[ob + 1] = r1;
        __syncthreads();
    }
}

// ----------------- K5: slice GEMM  slices[i] = a2wt @ W22[i] + terms --------
// grid 768 (i*256 + b*32 + t), 256 threads, 149KB dyn smem.
__global__ void k_slice(const float* __restrict__ W22) {
    extern __shared__ float sm[];
    float* wsh = sm;
    float* ash = sm + 24576;
    const int bid = blockIdx.x;
    const int i = bid >> 8, b = (bid >> 5) & 7, t = bid & 31;
    const int tid = threadIdx.x;
    const int warp = tid >> 5, lane = tid & 31;
    const int o0 = warp * 8;

    float bo[8];
#pragma unroll
    for (int e = 0; e < 8; e++) {
        const int o = o0 + e;
        bo[e] = g_R12[((i * 8 + b) * 32 + t) * 64 + o]
              + g_R12t[((i * 8 + b) * 32 + lane) * 64 + o]
              + g_R02b[(i * 8 + b) * 64 + o];
    }
    u64 acc0 = pk2(bo[0], bo[1]), acc1 = pk2(bo[2], bo[3]);
    u64 acc2 = pk2(bo[4], bo[5]), acc3 = pk2(bo[6], bo[7]);

    const float4* W4 = (const float4*)(W22 + i * 49152);
    const float4* A24 = (const float4*)g_A2;

    for (int tile = 0; tile < 2; tile++) {
        for (int idx = tid; idx < 6144; idx += 256)
            ((float4*)wsh)[idx] = W4[tile * 6144 + idx];
        for (int idx = tid; idx < 3072; idx += 256) {
            const int d = idx / 96, c4 = idx % 96;
            const int P = tile ? d : t, Q = tile ? t : d;
            const float4 v = A24[((b * 32 + P) * 32 + Q) * 96 + c4];
            const int cc = c4 * 4;
            ash[(cc + 0) * 33 + d] = v.x;
            ash[(cc + 1) * 33 + d] = v.y;
            ash[(cc + 2) * 33 + d] = v.z;
            ash[(cc + 3) * 33 + d] = v.w;
        }
        __syncthreads();
#pragma unroll 8
        for (int cc = 0; cc < 384; cc++) {
            const float* wr = wsh + cc * 64 + o0;
            const u64 w0 = *(const u64*)(wr + 0);
            const u64 w1 = *(const u64*)(wr + 2);
            const u64 w2 = *(const u64*)(wr + 4);
            const u64 w3 = *(const u64*)(wr + 6);
            const float xv = ash[cc * 33 + lane];
            const u64 xx = pk2(xv, xv);
            ffma2(acc0, xx, w0); ffma2(acc1, xx, w1);
            ffma2(acc2, xx, w2); ffma2(acc3, xx, w3);
        }
        __syncthreads();
    }
    float4 r0, r1;
    unpk(acc0, r0.x, r0.y); unpk(acc1, r0.z, r0.w);
    unpk(acc2, r1.x, r1.y); unpk(acc3, r1.z, r1.w);
    float4* S4 = (float4*)g_S;
    const int ob = (((i * 8 + b) * 32 + t) * 32 + lane) * 16 + (o0 >> 2);
    S4[ob] = r0; S4[ob + 1] = r1;
}

// ----------------- K6: diagonal scatter-add. grid 256, 256 threads ----------
__global__ void k_scatter(float* __restrict__ out) {
    const int bt = blockIdx.x;
    const int b = bt >> 5, t = bt & 31;
    const int tid = threadIdx.x;
    const int dg = tid >> 6, c = tid & 63;
    const float* S0 = g_S + ((0 * 8 + b) * 32 + t) * 2048;
    const float* S1 = g_S + ((1 * 8 + b) * 32 + t) * 2048;
    const float* S2 = g_S + ((2 * 8 + b) * 32 + t) * 2048;
    float* ob = out + b * 2097152;
    for (int d = dg; d < 32; d += 4) {
        const float s0 = S0[d * 64 + c], s1 = S1[d * 64 + c], s2 = S2[d * 64 + c];
        if (d != t) {
            ob[d * 65536 + d * 2048 + t * 64 + c] += s0;   // T[b,d,d,t]
            ob[d * 65536 + t * 2048 + d * 64 + c] += s1;   // T[b,d,t,d]
            ob[t * 65536 + d * 2048 + d * 64 + c] += s2;   // T[b,t,d,d]
        } else {
            ob[d * 65536 + d * 2048 + d * 64 + c] += s0 + s1 + s2 + g_Rmd[(b * 32 + d) * 64 + c];
        }
    }
}

// ---------------------------------------------------------------------------
extern "C" void kernel_launch(void* const* d_in, const int* in_sizes, int n_in,
                              void* d_out, int out_size) {
    const float* x    = (const float*)d_in[0];
    const float* W33  = (const float*)d_in[1];
    const float* b33  = (const float*)d_in[2];
    const float* W22  = (const float*)d_in[3];
    const float* b22  = (const float*)d_in[4];
    const float* W12  = (const float*)d_in[5];
    const float* b12  = (const float*)d_in[6];
    const float* W12t = (const float*)d_in[7];
    const float* b12t = (const float*)d_in[8];
    const float* W02  = (const float*)d_in[9];
    const float* b02  = (const float*)d_in[10];
    const float* W11  = (const float*)d_in[11];
    const float* b11  = (const float*)d_in[12];
    const float* W01  = (const float*)d_in[13];
    const float* b01  = (const float*)d_in[14];
    float* out = (float*)d_out;

    const size_t sm_main  = (24576 + 2 * 384 * 33) * sizeof(float);  // 199680
    const size_t sm_slice = (24576 + 384 * 33) * sizeof(float);      // 148992
    cudaFuncSetAttribute(k_main,  cudaFuncAttributeMaxDynamicSharedMemorySize, (int)sm_main);
    cudaFuncSetAttribute(k_slice, cudaFuncAttributeMaxDynamicSharedMemorySize, (int)sm_slice);

    k_contract<<<dim3(256, 3), 256>>>(x);
    k_a1<<<dim3(8, 10), 256>>>();
    k_a0<<<8, 256>>>();
    k_vec<<<dim3(256, 7), 256>>>(W12, b12, W12t, b12t, W02, b02, W11, b11, W01, b01, b22);
    k_main<<<148, 256, sm_main>>>(x, W33, b33, out);
    k_slice<<<768, 256, sm_slice>>>(W22);
    k_scatter<<<256, 256>>>(out);
}